// round 13
// baseline (speedup 1.0000x reference)
#include <cuda_runtime.h>

// Problem constants (fixed shapes: x = (2, 64, 256, 256) fp32, stoken_size = 16)
#define BB   2
#define CC   64
#define HH   256
#define WW   256
#define SS   16
#define NH   16
#define NW   16
#define NSP  256      // nH*nW
#define NPIX 65536    // H*W
#define NCTA 512      // BB*NSP — all co-resident (4 CTAs/SM x 148 = 592)

// packed-centroid layout: u64 cent2p[k][half][CP_STR]; value = (v,v).
#define CP_STR 36

typedef unsigned long long u64;

// Scratch (device globals; no allocations allowed)
__device__ float g_cent0[BB*NSP*CC];
// per-block partials: [b][blk][k(9)][c(64)]
__device__ float g_part [BB*NSP*9*64];
// per-block weight sums: [b][blk][k(9)]
__device__ float g_den0 [BB*NSP*9];
// grid barrier state (gen-based; self-resetting across graph replays)
__device__ unsigned g_cnt[2];
__device__ volatile unsigned g_gen[2];

// ---------------------------------------------------------------------------
// Packed f32x2 helpers (Blackwell FFMA2 path — PTX-only)
// ---------------------------------------------------------------------------
__device__ __forceinline__ u64 pack2(float lo, float hi) {
    u64 d; asm("mov.b64 %0, {%1,%2};" : "=l"(d) : "f"(lo), "f"(hi)); return d;
}
__device__ __forceinline__ float2 unpack2(u64 v) {
    float2 r; asm("mov.b64 {%0,%1}, %2;" : "=f"(r.x), "=f"(r.y) : "l"(v)); return r;
}
__device__ __forceinline__ u64 fma2(u64 a, u64 b, u64 c) {
    u64 d; asm("fma.rn.f32x2 %0, %1, %2, %3;" : "=l"(d) : "l"(a), "l"(b), "l"(c)); return d;
}
__device__ __forceinline__ u64 add2(u64 a, u64 b) {
    u64 d; asm("add.rn.f32x2 %0, %1, %2;" : "=l"(d) : "l"(a), "l"(b)); return d;
}

// ---------------------------------------------------------------------------
// Grid barrier (generation/sense based; safe across graph replays).
// All NCTA CTAs are co-resident by the occupancy bound, so no deadlock.
// ---------------------------------------------------------------------------
__device__ __forceinline__ void grid_barrier(int i)
{
    __syncthreads();
    if (threadIdx.x == 0) {
        __threadfence();
        unsigned my  = g_gen[i];
        unsigned arr = atomicAdd(&g_cnt[i], 1u);
        if (arr == NCTA - 1u) {
            g_cnt[i] = 0u;           // reset for the next launch/replay
            __threadfence();
            g_gen[i] = my + 1u;      // release all spinners
        } else {
            while (g_gen[i] == my) { __nanosleep(64); }
        }
        __threadfence();
    }
    __syncthreads();
}

// ---------------------------------------------------------------------------
// Zero the cold region of output plane (b,s) — everything OUTSIDE the 3x3
// block-neighborhood footprint, which the phase-5 scatters cover exactly.
// Address-disjoint from all scatters -> race-free, fire-and-forget.
// ---------------------------------------------------------------------------
__device__ __forceinline__ void zero_plane_cold(float* __restrict__ out,
                                                int b, int s, int tid)
{
    int sy = s >> 4, sx = s & 15;
    int hy0 = (sy > 0)  ? (sy-1)*16 : 0;
    int hy1 = (sy < 15) ? (sy+2)*16 : 256;
    int hx0 = ((sx > 0)  ? (sx-1)*16 : 0) >> 2;
    int hx1 = ((sx < 15) ? (sx+2)*16 : 256) >> 2;
    float4* plane = (float4*)(out + ((size_t)(b*NSP + s) << 16));
    float4 z = make_float4(0.f, 0.f, 0.f, 0.f);
    #pragma unroll 4
    for (int i = tid; i < 256*64; i += 256) {
        int y = i >> 6, xf = i & 63;
        if (y < hy0 || y >= hy1 || xf < hx0 || xf >= hx1)
            __stcs(&plane[i], z);
    }
}

// ---------------------------------------------------------------------------
// Packed pixel-pair dots: 32 LDG.64 + 36 LDS.128 + 288 FFMA2 per thread.
// ---------------------------------------------------------------------------
__device__ __forceinline__ void dot9p2(const float* xp, const u64* centp,
                                       int h, u64 acc2[9])
{
    #pragma unroll
    for (int k = 0; k < 9; k++) acc2[k] = 0ull;

    #pragma unroll
    for (int c8 = 0; c8 < 4; c8++) {
        u64 p2[8];
        #pragma unroll
        for (int i = 0; i < 8; i++)
            p2[i] = *(const u64*)(xp + (size_t)(c8*8 + i)*NPIX);
        #pragma unroll
        for (int k = 0; k < 9; k++) {
            const ulonglong2* cv = (const ulonglong2*)(centp + (k*2 + h)*CP_STR + c8*8);
            #pragma unroll
            for (int i2 = 0; i2 < 4; i2++) {
                ulonglong2 q = cv[i2];
                acc2[k] = fma2(p2[i2*2 + 0], q.x, acc2[k]);
                acc2[k] = fma2(p2[i2*2 + 1], q.y, acc2[k]);
            }
        }
    }
    #pragma unroll
    for (int k = 0; k < 9; k++) {
        u64 o = __shfl_xor_sync(0xffffffffu, acc2[k], 1);
        acc2[k] = add2(acc2[k], o);
    }
}

// ---------------------------------------------------------------------------
// Softmax for this thread's pixel.
// ---------------------------------------------------------------------------
__device__ __forceinline__ void softmax9(const float* dot, const float* csq_s,
                                         int sy, int sx, float* e)
{
    float l[9];
    float m = -1e30f;
    #pragma unroll
    for (int k = 0; k < 9; k++) {
        int cy = sy + (k/3) - 1, cx = sx + (k%3) - 1;
        bool valid = (cy >= 0 && cy < NH && cx >= 0 && cx < NW);
        l[k] = valid ? (2.f*dot[k] - csq_s[k]) : -1e30f;
        m = fmaxf(m, l[k]);
    }
    float ssum = 0.f;
    #pragma unroll
    for (int k = 0; k < 9; k++) {
        e[k] = (l[k] > -1e29f) ? __expf(l[k] - m) : 0.f;
        ssum += e[k];
    }
    float inv = 1.f / ssum;
    #pragma unroll
    for (int k = 0; k < 9; k++) e[k] *= inv;
}

// ---------------------------------------------------------------------------
// csq helper: |c|^2 for the 9 staged candidates (from packed smem).
// ---------------------------------------------------------------------------
__device__ __forceinline__ void compute_csq(const u64* cent2p, float* csq_s, int tid)
{
    if (tid < 18) {
        int k = tid >> 1, h = tid & 1;
        float s = 0.f;
        #pragma unroll 8
        for (int c = 0; c < 32; c++) {
            float2 t = unpack2(cent2p[(k*2 + h)*CP_STR + c]);
            s = fmaf(t.x, t.x, s);
        }
        if (h == 0) csq_s[k] = s;
        __syncwarp(0x0003ffffu);
        if (h == 1) csq_s[k] += s;
    }
}

// ---------------------------------------------------------------------------
// THE kernel: 512 co-resident CTAs, one per (b, block). Phases:
//  0: zero own plane's cold region (fire-and-forget, drains all kernel long)
//  1: block means from own pixels -> g_cent0           | grid barrier
//  2: iteration-0 weights + partials -> g_part/g_den0  | grid barrier
//  3: updated centroids (gathered in-CTA) + final weights -> scatter to out
// ---------------------------------------------------------------------------
__global__ void __launch_bounds__(256, 4) k_fused(const float* __restrict__ x,
                                                  float* __restrict__ out)
{
    __shared__ __align__(16) u64 cent2p[9*2*CP_STR];
    __shared__ float csq_s[9];
    __shared__ float dens[9];
    __shared__ u64   Wsh2[256*9];        // packed (w,w)
    __shared__ float dsm[8][9];
    __shared__ float wsum[8][2][32];     // means reduction: [warp][h][chan]

    int tid = threadIdx.x;
    int bid = blockIdx.x;
    int b   = bid >> 8;
    int blk = bid & 255;
    int sy  = blk >> 4, sx = blk & 15;

    // ---- phase 0: streaming zeros of own plane's cold region ----
    zero_plane_cold(out, b, blk, tid);

    // ---- phase 1: block means from this CTA's own pixels ----
    int pp  = tid >> 1;                 // pixel pair 0..127
    int h   = tid & 1;                  // channel half
    int row = pp >> 3;
    int col2= (pp & 7)*2;
    int n0  = (sy*SS + row)*WW + sx*SS + col2;
    const float* xp = x + (size_t)b*CC*NPIX + (size_t)(h*32)*NPIX + n0;
    int wid = tid >> 5, lane = tid & 31;

    #pragma unroll
    for (int i = 0; i < 32; i++) {
        float2 v = *(const float2*)(xp + (size_t)i*NPIX);
        float s = v.x + v.y;
        s += __shfl_xor_sync(0xffffffffu, s, 2);
        s += __shfl_xor_sync(0xffffffffu, s, 4);
        s += __shfl_xor_sync(0xffffffffu, s, 8);
        s += __shfl_xor_sync(0xffffffffu, s, 16);
        if (lane < 2) wsum[wid][lane][i] = s;
    }
    __syncthreads();
    if (tid < 64) {
        int hh = tid >> 5, ii = tid & 31;
        float s = 0.f;
        #pragma unroll
        for (int w = 0; w < 8; w++) s += wsum[w][hh][ii];
        g_cent0[((size_t)(b*NSP + blk))*CC + tid] = s * (1.f/256.f);
    }

    grid_barrier(0);

    // ---- phase 2: iteration 0 (stage neighbor means, dots, softmax, partials) ----
    for (int i = tid; i < 9*64; i += 256) {
        int k = i >> 6, c = i & 63;
        int cy = sy + (k/3) - 1, cx = sx + (k%3) - 1;
        float v = 0.f;
        if (cy >= 0 && cy < NH && cx >= 0 && cx < NW)
            v = g_cent0[((size_t)(b*NSP + cy*NW + cx))*CC + c];
        cent2p[(k*2 + (c >> 5))*CP_STR + (c & 31)] = pack2(v, v);
    }
    __syncthreads();
    compute_csq(cent2p, csq_s, tid);
    __syncthreads();

    {
        u64 acc2[9];
        dot9p2(xp, cent2p, h, acc2);

        float dot[9];
        #pragma unroll
        for (int k = 0; k < 9; k++) {
            float2 d = unpack2(acc2[k]);
            dot[k] = h ? d.y : d.x;
        }

        float e[9];
        softmax9(dot, csq_s, sy, sx, e);

        // pix == tid (pp*2+h)
        #pragma unroll
        for (int k = 0; k < 9; k++) Wsh2[tid*9 + k] = pack2(e[k], e[k]);

        // den[k] over all 256 pixels
        #pragma unroll
        for (int k = 0; k < 9; k++) {
            float v = e[k];
            #pragma unroll
            for (int o = 16; o > 0; o >>= 1) v += __shfl_xor_sync(0xffffffffu, v, o);
            if (lane == 0) dsm[wid][k] = v;
        }
        __syncthreads();
        if (tid < 9) {
            float s = 0.f;
            #pragma unroll
            for (int w = 0; w < 8; w++) s += dsm[w][tid];
            g_den0[((size_t)(b*NSP + blk))*9 + tid] = s;
        }

        // partials: warp wid -> channels [wid*8, wid*8+8) (packed FFMA2)
        const float* xt = x + (size_t)b*CC*NPIX + (size_t)(sy*SS)*WW + sx*SS;
        float* pdst = g_part + ((size_t)(b*NSP + blk)*9)*64;

        #pragma unroll
        for (int grp = 0; grp < 2; grp++) {
            int cbase = wid*8 + grp*4;
            u64 acc2c[2][9];
            #pragma unroll
            for (int cc = 0; cc < 2; cc++)
                #pragma unroll
                for (int k = 0; k < 9; k++) acc2c[cc][k] = 0ull;

            #pragma unroll
            for (int j = 0; j < 8; j++) {
                int px = j*32 + lane;
                int prow = px >> 4, pcol = px & 15;
                u64 w2[9];
                #pragma unroll
                for (int k = 0; k < 9; k++) w2[k] = Wsh2[px*9 + k];
                #pragma unroll
                for (int cc = 0; cc < 2; cc++) {
                    float pv0 = xt[(size_t)(cbase + 2*cc + 0)*NPIX + prow*WW + pcol];
                    float pv1 = xt[(size_t)(cbase + 2*cc + 1)*NPIX + prow*WW + pcol];
                    u64 pv2 = pack2(pv0, pv1);
                    #pragma unroll
                    for (int k = 0; k < 9; k++)
                        acc2c[cc][k] = fma2(pv2, w2[k], acc2c[cc][k]);
                }
            }
            float acc[4][9];
            #pragma unroll
            for (int cc = 0; cc < 2; cc++)
                #pragma unroll
                for (int k = 0; k < 9; k++) {
                    float2 a = unpack2(acc2c[cc][k]);
                    acc[2*cc][k] = a.x; acc[2*cc+1][k] = a.y;
                }
            #pragma unroll
            for (int cc = 0; cc < 4; cc++)
                #pragma unroll
                for (int k = 0; k < 9; k++)
                    #pragma unroll
                    for (int o = 16; o > 0; o >>= 1)
                        acc[cc][k] += __shfl_xor_sync(0xffffffffu, acc[cc][k], o);
            #pragma unroll
            for (int k = 0; k < 9; k++) {
                if (lane == k) {
                    #pragma unroll
                    for (int cc = 0; cc < 4; cc++)
                        pdst[(size_t)k*64 + cbase + cc] = acc[cc][k];
                }
            }
        }
    }

    grid_barrier(1);

    // ---- phase 3: updated centroids (in-CTA gather) + final weights + scatter ----
    if (tid < 9) {
        int cy = sy + tid/3 - 1, cx = sx + tid%3 - 1;
        float d = 0.f;
        if (cy >= 0 && cy < NH && cx >= 0 && cx < NW) {
            #pragma unroll
            for (int j = 0; j < 9; j++) {
                int ny = cy + j/3 - 1, nx = cx + j%3 - 1;
                if (ny >= 0 && ny < NH && nx >= 0 && nx < NW)
                    d += g_den0[((size_t)(b*NSP + ny*NW + nx))*9 + (8 - j)];
            }
        }
        dens[tid] = d + 1e-16f;
    }
    __syncthreads();

    for (int i = tid; i < 9*64; i += 256) {
        int k = i >> 6, c = i & 63;
        int cy = sy + k/3 - 1, cx = sx + k%3 - 1;
        float v = 0.f;
        if (cy >= 0 && cy < NH && cx >= 0 && cx < NW) {
            float num = 0.f;
            #pragma unroll
            for (int j = 0; j < 9; j++) {
                int ny = cy + j/3 - 1, nx = cx + j%3 - 1;
                if (ny >= 0 && ny < NH && nx >= 0 && nx < NW)
                    num += g_part[((size_t)((b*NSP + ny*NW + nx)*9 + (8 - j)))*64 + c];
            }
            v = num / dens[k];
        }
        cent2p[(k*2 + (c >> 5))*CP_STR + (c & 31)] = pack2(v, v);
    }
    __syncthreads();
    compute_csq(cent2p, csq_s, tid);
    __syncthreads();

    {
        u64 acc2[9];
        dot9p2(xp, cent2p, h, acc2);

        float dot[9];
        #pragma unroll
        for (int k = 0; k < 9; k++) {
            float2 d = unpack2(acc2[k]);
            dot[k] = h ? d.y : d.x;
        }

        int n = n0 + h;
        float e[9];
        softmax9(dot, csq_s, sy, sx, e);

        float* obase = out + ((size_t)b*NSP << 16);
        #pragma unroll
        for (int k = 0; k < 9; k++) {
            int cy = sy + (k/3) - 1, cx = sx + (k%3) - 1;
            if (cy >= 0 && cy < NH && cx >= 0 && cx < NW)
                __stcs(&obase[((size_t)(cy*NW + cx) << 16) + n], e[k]);
        }
    }
}

// ---------------------------------------------------------------------------
extern "C" void kernel_launch(void* const* d_in, const int* in_sizes, int n_in,
                              void* d_out, int out_size)
{
    const float* x = (const float*)d_in[0];
    float* out = (float*)d_out;

    k_fused<<<NCTA, 256>>>(x, out);
}

// round 14
// speedup vs baseline: 2.4678x; 2.4678x over previous
#include <cuda_runtime.h>

// Problem constants (fixed shapes: x = (2, 64, 256, 256) fp32, stoken_size = 16)
#define BB   2
#define CC   64
#define HH   256
#define WW   256
#define SS   16
#define NH   16
#define NW   16
#define NSP  256      // nH*nW
#define NPIX 65536    // H*W

// packed-centroid layout: u64 cent2p[k][half][CP_STR]; value = (v,v).
#define CP_STR 36

typedef unsigned long long u64;

// Scratch (device globals; no allocations allowed)
__device__ float g_cent0[BB*NSP*CC];
__device__ float g_cent1[BB*NSP*CC];
// per-block partials: [b][blk][k(9)][c(64)]
__device__ float g_part [BB*NSP*9*64];
// per-block weight sums: [b][blk][k(9)]
__device__ float g_den0 [BB*NSP*9];

// ---------------------------------------------------------------------------
// Packed f32x2 helpers (Blackwell FFMA2 path — PTX-only)
// ---------------------------------------------------------------------------
__device__ __forceinline__ u64 pack2(float lo, float hi) {
    u64 d; asm("mov.b64 %0, {%1,%2};" : "=l"(d) : "f"(lo), "f"(hi)); return d;
}
__device__ __forceinline__ float2 unpack2(u64 v) {
    float2 r; asm("mov.b64 {%0,%1}, %2;" : "=f"(r.x), "=f"(r.y) : "l"(v)); return r;
}
__device__ __forceinline__ u64 fma2(u64 a, u64 b, u64 c) {
    u64 d; asm("fma.rn.f32x2 %0, %1, %2, %3;" : "=l"(d) : "l"(a), "l"(b), "l"(c)); return d;
}
__device__ __forceinline__ u64 add2(u64 a, u64 b) {
    u64 d; asm("add.rn.f32x2 %0, %1, %2;" : "=l"(d) : "l"(a), "l"(b)); return d;
}

// ---------------------------------------------------------------------------
// Zero rows [ya, yb) of output plane (b,s), COLD region only: the hot 3x3
// block-neighborhood footprint is exactly covered by k_final's scatters,
// so zeros and scatters are address-disjoint (race-free, order-free).
// ---------------------------------------------------------------------------
__device__ __forceinline__ void zero_plane_rows(float* __restrict__ out,
                                                int b, int s,
                                                int ya, int yb, int tid)
{
    int sy = s >> 4, sx = s & 15;
    int hy0 = (sy > 0)  ? (sy-1)*16 : 0;
    int hy1 = (sy < 15) ? (sy+2)*16 : 256;
    int hx0 = ((sx > 0)  ? (sx-1)*16 : 0) >> 2;
    int hx1 = ((sx < 15) ? (sx+2)*16 : 256) >> 2;
    float4* plane = (float4*)(out + ((size_t)(b*NSP + s) << 16));
    float4 z = make_float4(0.f, 0.f, 0.f, 0.f);
    for (int i = ya*64 + tid; i < yb*64; i += 256) {
        int y = i >> 6, xf = i & 63;
        if (y < hy0 || y >= hy1 || xf < hx0 || xf >= hx1)
            __stcs(&plane[i], z);
    }
}

// ---------------------------------------------------------------------------
// K1: zero rows [0,104) (4 CTAs/plane, 26 rows each) + per-block means.
// CTA = (b, c, block-row by). 2048 CTAs, 256 threads, coalesced LDG.128.
// ---------------------------------------------------------------------------
__global__ __launch_bounds__(256) void k_means(const float* __restrict__ x,
                                               float* __restrict__ out)
{
    int tid = threadIdx.x;
    int bid = blockIdx.x;

    // zeros first (fire-and-forget): plane = bid&511, quarter = bid>>9
    {
        int zp = bid & 511;
        int q  = bid >> 9;
        zero_plane_rows(out, zp >> 8, zp & 255, q*26, q*26 + 26, tid);
    }

    int by  = bid & 15;
    int bc  = bid >> 4;          // b*64 + c
    int b   = bc >> 6, c = bc & 63;

    const float4* xp = (const float4*)(x + (size_t)bc*NPIX + (size_t)by*16*WW);
    int fc  = tid & 63;          // float4 column 0..63
    int g   = tid >> 6;          // row group 0..3

    float4 s = make_float4(0.f, 0.f, 0.f, 0.f);
    #pragma unroll
    for (int r = 0; r < 4; r++) {
        float4 v = xp[(g*4 + r)*64 + fc];
        s.x += v.x; s.y += v.y; s.z += v.z; s.w += v.w;
    }

    __shared__ float4 sm4[4][64];
    __shared__ float  smc[64];
    sm4[g][fc] = s;
    __syncthreads();

    if (tid < 64) {
        float4 a = sm4[0][tid], b4 = sm4[1][tid], c4 = sm4[2][tid], d4 = sm4[3][tid];
        smc[tid] = (a.x+a.y+a.z+a.w) + (b4.x+b4.y+b4.z+b4.w)
                 + (c4.x+c4.y+c4.z+c4.w) + (d4.x+d4.y+d4.z+d4.w);
    }
    __syncthreads();

    if (tid < 16) {
        float m = (smc[4*tid] + smc[4*tid+1] + smc[4*tid+2] + smc[4*tid+3]) * (1.f/256.f);
        g_cent0[((size_t)(b*NSP + by*16 + tid))*CC + c] = m;
    }
}

// ---------------------------------------------------------------------------
// Stage 9 candidate centroids as packed (v,v) u64 pairs + csq.
// ---------------------------------------------------------------------------
__device__ __forceinline__ void stage_cent2p(const float* __restrict__ cent,
                                             u64* cent2p, float* csq_s,
                                             int b, int sy, int sx, int tid)
{
    for (int i = tid; i < 9*64; i += 256) {
        int k = i >> 6, c = i & 63;
        int cy = sy + (k/3) - 1, cx = sx + (k%3) - 1;
        float v = 0.f;
        if (cy >= 0 && cy < NH && cx >= 0 && cx < NW)
            v = cent[((size_t)(b*NSP + cy*NW + cx))*CC + c];
        cent2p[(k*2 + (c >> 5))*CP_STR + (c & 31)] = pack2(v, v);
    }
    __syncthreads();
    if (tid < 18) {
        int k = tid >> 1, h = tid & 1;
        float s = 0.f;
        #pragma unroll 8
        for (int c = 0; c < 32; c++) {
            float2 t = unpack2(cent2p[(k*2 + h)*CP_STR + c]);
            s = fmaf(t.x, t.x, s);
        }
        if (h == 0) csq_s[k] = s;
        __syncwarp(0x0003ffffu);
        if (h == 1) csq_s[k] += s;
    }
    __syncthreads();
}

// ---------------------------------------------------------------------------
// Packed pixel-pair dots: 32 LDG.64 + 36 LDS.128 + 288 FFMA2 per thread.
// ---------------------------------------------------------------------------
__device__ __forceinline__ void dot9p2(const float* xp, const u64* centp,
                                       int h, u64 acc2[9])
{
    #pragma unroll
    for (int k = 0; k < 9; k++) acc2[k] = 0ull;

    #pragma unroll
    for (int c8 = 0; c8 < 4; c8++) {
        u64 p2[8];
        #pragma unroll
        for (int i = 0; i < 8; i++)
            p2[i] = *(const u64*)(xp + (size_t)(c8*8 + i)*NPIX);
        #pragma unroll
        for (int k = 0; k < 9; k++) {
            const ulonglong2* cv = (const ulonglong2*)(centp + (k*2 + h)*CP_STR + c8*8);
            #pragma unroll
            for (int i2 = 0; i2 < 4; i2++) {
                ulonglong2 q = cv[i2];
                acc2[k] = fma2(p2[i2*2 + 0], q.x, acc2[k]);
                acc2[k] = fma2(p2[i2*2 + 1], q.y, acc2[k]);
            }
        }
    }
    #pragma unroll
    for (int k = 0; k < 9; k++) {
        u64 o = __shfl_xor_sync(0xffffffffu, acc2[k], 1);
        acc2[k] = add2(acc2[k], o);
    }
}

// ---------------------------------------------------------------------------
// Softmax for this thread's pixel.
// ---------------------------------------------------------------------------
__device__ __forceinline__ void softmax9(const float* dot, const float* csq_s,
                                         int sy, int sx, float* e)
{
    float l[9];
    float m = -1e30f;
    #pragma unroll
    for (int k = 0; k < 9; k++) {
        int cy = sy + (k/3) - 1, cx = sx + (k%3) - 1;
        bool valid = (cy >= 0 && cy < NH && cx >= 0 && cx < NW);
        l[k] = valid ? (2.f*dot[k] - csq_s[k]) : -1e30f;
        m = fmaxf(m, l[k]);
    }
    float ssum = 0.f;
    #pragma unroll
    for (int k = 0; k < 9; k++) {
        e[k] = (l[k] > -1e29f) ? __expf(l[k] - m) : 0.f;
        ssum += e[k];
    }
    float inv = 1.f / ssum;
    #pragma unroll
    for (int k = 0; k < 9; k++) e[k] *= inv;
}

// ---------------------------------------------------------------------------
// K2: zero rows [104,176) of its plane + iteration 0 over FULL blocks.
// 512 CTAs, 256 threads: thread = (pp 0..127, h 0..1); pix == tid.
// ---------------------------------------------------------------------------
__global__ __launch_bounds__(256) void k_iter0(const float* __restrict__ x,
                                               float* __restrict__ out)
{
    __shared__ __align__(16) u64 cent2p[9*2*CP_STR];
    __shared__ float csq_s[9];
    __shared__ u64 Wsh2[256*9];          // packed (w,w)
    __shared__ float dsm[8][9];

    int tid = threadIdx.x;
    int bid = blockIdx.x;
    int b   = bid >> 8;
    int blk = bid & 255;
    int sy  = blk >> 4, sx = blk & 15;

    zero_plane_rows(out, b, blk, 104, 176, tid);

    stage_cent2p(g_cent0, cent2p, csq_s, b, sy, sx, tid);

    // phase B
    int pp  = tid >> 1;                 // pixel pair 0..127
    int h   = tid & 1;                  // channel half
    int row = pp >> 3;
    int col2= (pp & 7)*2;
    int n0  = (sy*SS + row)*WW + sx*SS + col2;
    const float* xp = x + (size_t)b*CC*NPIX + (size_t)(h*32)*NPIX + n0;

    u64 acc2[9];
    dot9p2(xp, cent2p, h, acc2);

    float dot[9];
    #pragma unroll
    for (int k = 0; k < 9; k++) {
        float2 d = unpack2(acc2[k]);
        dot[k] = h ? d.y : d.x;
    }

    float e[9];
    softmax9(dot, csq_s, sy, sx, e);

    // pix == tid
    #pragma unroll
    for (int k = 0; k < 9; k++) Wsh2[tid*9 + k] = pack2(e[k], e[k]);

    // den[k] over all 256 pixels
    {
        int wid = tid >> 5, lane = tid & 31;
        #pragma unroll
        for (int k = 0; k < 9; k++) {
            float v = e[k];
            #pragma unroll
            for (int o = 16; o > 0; o >>= 1) v += __shfl_xor_sync(0xffffffffu, v, o);
            if (lane == 0) dsm[wid][k] = v;
        }
        __syncthreads();
        if (tid < 9) {
            float s = 0.f;
            #pragma unroll
            for (int w = 0; w < 8; w++) s += dsm[w][tid];
            g_den0[((size_t)(b*NSP + blk))*9 + tid] = s;
        }
    }

    // phase C (packed): warp wid -> channels [wid*8, wid*8+8).
    int wid = tid >> 5, lane = tid & 31;
    const float* xt = x + (size_t)b*CC*NPIX + (size_t)(sy*SS)*WW + sx*SS;
    float* pdst = g_part + ((size_t)(b*NSP + blk)*9)*64;

    #pragma unroll
    for (int grp = 0; grp < 2; grp++) {
        int cbase = wid*8 + grp*4;
        u64 acc2c[2][9];
        #pragma unroll
        for (int cc = 0; cc < 2; cc++)
            #pragma unroll
            for (int k = 0; k < 9; k++) acc2c[cc][k] = 0ull;

        #pragma unroll
        for (int j = 0; j < 8; j++) {
            int px = j*32 + lane;
            int prow = px >> 4, pcol = px & 15;
            u64 w2[9];
            #pragma unroll
            for (int k = 0; k < 9; k++) w2[k] = Wsh2[px*9 + k];
            #pragma unroll
            for (int cc = 0; cc < 2; cc++) {
                float pv0 = xt[(size_t)(cbase + 2*cc + 0)*NPIX + prow*WW + pcol];
                float pv1 = xt[(size_t)(cbase + 2*cc + 1)*NPIX + prow*WW + pcol];
                u64 pv2 = pack2(pv0, pv1);
                #pragma unroll
                for (int k = 0; k < 9; k++)
                    acc2c[cc][k] = fma2(pv2, w2[k], acc2c[cc][k]);
            }
        }
        float acc[4][9];
        #pragma unroll
        for (int cc = 0; cc < 2; cc++)
            #pragma unroll
            for (int k = 0; k < 9; k++) {
                float2 a = unpack2(acc2c[cc][k]);
                acc[2*cc][k] = a.x; acc[2*cc+1][k] = a.y;
            }
        #pragma unroll
        for (int cc = 0; cc < 4; cc++)
            #pragma unroll
            for (int k = 0; k < 9; k++)
                #pragma unroll
                for (int o = 16; o > 0; o >>= 1)
                    acc[cc][k] += __shfl_xor_sync(0xffffffffu, acc[cc][k], o);
        #pragma unroll
        for (int k = 0; k < 9; k++) {
            if (lane == k) {
                #pragma unroll
                for (int cc = 0; cc < 4; cc++)
                    pdst[(size_t)k*64 + cbase + cc] = acc[cc][k];
            }
        }
    }
}

// ---------------------------------------------------------------------------
// K3: zero rows [176,208) + gather centroid update (no atomics).
// grid = 512 (b,s), block = 256 (tid<64 compute; all threads zero).
// ---------------------------------------------------------------------------
__global__ __launch_bounds__(256) void k_update(float* __restrict__ out)
{
    int tid = threadIdx.x;
    int bid = blockIdx.x;
    int b   = bid >> 8;
    int s   = bid & 255;
    int sy  = s >> 4, sx = s & 15;

    zero_plane_rows(out, b, s, 176, 208, tid);

    __shared__ float dsm[9];
    if (tid < 9) {
        int dy = tid/3 - 1, dx = tid%3 - 1;
        int ny = sy + dy, nx = sx + dx;
        float d = 0.f;
        if (ny >= 0 && ny < NH && nx >= 0 && nx < NW)
            d = g_den0[((size_t)(b*NSP + ny*NW + nx))*9 + (8 - tid)];
        dsm[tid] = d;
    }
    __syncthreads();

    if (tid < 64) {
        int c = tid;
        float den = 0.f;
        #pragma unroll
        for (int j = 0; j < 9; j++) den += dsm[j];

        float num = 0.f;
        #pragma unroll
        for (int j = 0; j < 9; j++) {
            int dy = j/3 - 1, dx = j%3 - 1;
            int ny = sy + dy, nx = sx + dx;
            if (ny >= 0 && ny < NH && nx >= 0 && nx < NW)
                num += g_part[((size_t)((b*NSP + ny*NW + nx)*9 + (8 - j)))*64 + c];
        }
        g_cent1[((size_t)(b*NSP + s))*CC + c] = num / (den + 1e-16f);
    }
}

// ---------------------------------------------------------------------------
// K4: zero rows [208,256) of its plane + final weights, scattered
// (evict-first) into the output. 512 CTAs, 256 threads, pixel-pair mapping.
// ---------------------------------------------------------------------------
__global__ __launch_bounds__(256) void k_final(const float* __restrict__ x,
                                               float* __restrict__ out)
{
    __shared__ __align__(16) u64 cent2p[9*2*CP_STR];
    __shared__ float csq_s[9];

    int bid = blockIdx.x;
    int b   = bid >> 8;
    int blk = bid & 255;
    int sy  = blk >> 4, sx = blk & 15;
    int tid = threadIdx.x;

    zero_plane_rows(out, b, blk, 208, 256, tid);

    stage_cent2p(g_cent1, cent2p, csq_s, b, sy, sx, tid);

    int pp  = tid >> 1;
    int h   = tid & 1;
    int row = pp >> 3;
    int col2= (pp & 7)*2;
    int n0  = (sy*SS + row)*WW + sx*SS + col2;
    const float* xp = x + (size_t)b*CC*NPIX + (size_t)(h*32)*NPIX + n0;

    u64 acc2[9];
    dot9p2(xp, cent2p, h, acc2);

    float dot[9];
    #pragma unroll
    for (int k = 0; k < 9; k++) {
        float2 d = unpack2(acc2[k]);
        dot[k] = h ? d.y : d.x;
    }

    int n = n0 + h;                     // this thread's pixel index
    float e[9];
    softmax9(dot, csq_s, sy, sx, e);

    float* obase = out + ((size_t)b*NSP << 16);
    #pragma unroll
    for (int k = 0; k < 9; k++) {
        int cy = sy + (k/3) - 1, cx = sx + (k%3) - 1;
        if (cy >= 0 && cy < NH && cx >= 0 && cx < NW)
            __stcs(&obase[((size_t)(cy*NW + cx) << 16) + n], e[k]);
    }
}

// ---------------------------------------------------------------------------
extern "C" void kernel_launch(void* const* d_in, const int* in_sizes, int n_in,
                              void* d_out, int out_size)
{
    const float* x = (const float*)d_in[0];
    float* out = (float*)d_out;

    k_means <<<BB*CC*16, 256>>>(x, out);
    k_iter0 <<<BB*NSP,   256>>>(x, out);
    k_update<<<BB*NSP,   256>>>(out);
    k_final <<<BB*NSP,   256>>>(x, out);
}

// round 15
// speedup vs baseline: 2.5469x; 1.0320x over previous
#include <cuda_runtime.h>

// Problem constants (fixed shapes: x = (2, 64, 256, 256) fp32, stoken_size = 16)
#define BB   2
#define CC   64
#define HH   256
#define WW   256
#define SS   16
#define NH   16
#define NW   16
#define NSP  256      // nH*nW
#define NPIX 65536    // H*W

// packed-centroid layout: u64 cent2p[k][half][CP_STR]; value = (v,v).
#define CP_STR 36

typedef unsigned long long u64;

// Scratch (device globals; no allocations allowed)
__device__ float g_cent0[BB*NSP*CC];
__device__ float g_cent1[BB*NSP*CC];
// per-block partials: [b][blk][k(9)][c(64)]
__device__ float g_part [BB*NSP*9*64];
// per-block weight sums: [b][blk][k(9)]
__device__ float g_den0 [BB*NSP*9];

// ---------------------------------------------------------------------------
// Packed f32x2 helpers (Blackwell FFMA2 path — PTX-only)
// ---------------------------------------------------------------------------
__device__ __forceinline__ u64 pack2(float lo, float hi) {
    u64 d; asm("mov.b64 %0, {%1,%2};" : "=l"(d) : "f"(lo), "f"(hi)); return d;
}
__device__ __forceinline__ float2 unpack2(u64 v) {
    float2 r; asm("mov.b64 {%0,%1}, %2;" : "=f"(r.x), "=f"(r.y) : "l"(v)); return r;
}
__device__ __forceinline__ u64 fma2(u64 a, u64 b, u64 c) {
    u64 d; asm("fma.rn.f32x2 %0, %1, %2, %3;" : "=l"(d) : "l"(a), "l"(b), "l"(c)); return d;
}
__device__ __forceinline__ u64 add2(u64 a, u64 b) {
    u64 d; asm("add.rn.f32x2 %0, %1, %2;" : "=l"(d) : "l"(a), "l"(b)); return d;
}

// ---------------------------------------------------------------------------
// K1: zero-fill (64 MB, evict-first) + per-block channel means.
// CTA = (b, c, block-row by). 2048 CTAs, 256 threads, coalesced LDG.128.
// ---------------------------------------------------------------------------
__global__ __launch_bounds__(256) void k_means(const float* __restrict__ x,
                                               float* __restrict__ out)
{
    int tid = threadIdx.x;
    int bid = blockIdx.x;

    // streaming zero stores — out4[0 .. 4194304)
    {
        float4 z = make_float4(0.f, 0.f, 0.f, 0.f);
        float4* oz = (float4*)out + (size_t)bid*2048;
        #pragma unroll
        for (int j = 0; j < 8; j++) __stcs(&oz[j*256 + tid], z);
    }

    int by  = bid & 15;
    int bc  = bid >> 4;          // b*64 + c
    int b   = bc >> 6, c = bc & 63;

    const float4* xp = (const float4*)(x + (size_t)bc*NPIX + (size_t)by*16*WW);
    int fc  = tid & 63;          // float4 column 0..63
    int g   = tid >> 6;          // row group 0..3

    float4 s = make_float4(0.f, 0.f, 0.f, 0.f);
    #pragma unroll
    for (int r = 0; r < 4; r++) {
        float4 v = xp[(g*4 + r)*64 + fc];
        s.x += v.x; s.y += v.y; s.z += v.z; s.w += v.w;
    }

    __shared__ float4 sm4[4][64];
    __shared__ float  smc[64];
    sm4[g][fc] = s;
    __syncthreads();

    if (tid < 64) {
        float4 a = sm4[0][tid], b4 = sm4[1][tid], c4 = sm4[2][tid], d4 = sm4[3][tid];
        smc[tid] = (a.x+a.y+a.z+a.w) + (b4.x+b4.y+b4.z+b4.w)
                 + (c4.x+c4.y+c4.z+c4.w) + (d4.x+d4.y+d4.z+d4.w);
    }
    __syncthreads();

    if (tid < 16) {
        float m = (smc[4*tid] + smc[4*tid+1] + smc[4*tid+2] + smc[4*tid+3]) * (1.f/256.f);
        g_cent0[((size_t)(b*NSP + by*16 + tid))*CC + c] = m;
    }
}

// ---------------------------------------------------------------------------
// Stage 9 candidate centroids as packed (v,v) u64 pairs + csq.
// ---------------------------------------------------------------------------
__device__ __forceinline__ void stage_cent2p(const float* __restrict__ cent,
                                             u64* cent2p, float* csq_s,
                                             int b, int sy, int sx, int tid)
{
    for (int i = tid; i < 9*64; i += 256) {
        int k = i >> 6, c = i & 63;
        int cy = sy + (k/3) - 1, cx = sx + (k%3) - 1;
        float v = 0.f;
        if (cy >= 0 && cy < NH && cx >= 0 && cx < NW)
            v = cent[((size_t)(b*NSP + cy*NW + cx))*CC + c];
        cent2p[(k*2 + (c >> 5))*CP_STR + (c & 31)] = pack2(v, v);
    }
    __syncthreads();
    if (tid < 18) {
        int k = tid >> 1, h = tid & 1;
        float s = 0.f;
        #pragma unroll 8
        for (int c = 0; c < 32; c++) {
            float2 t = unpack2(cent2p[(k*2 + h)*CP_STR + c]);
            s = fmaf(t.x, t.x, s);
        }
        if (h == 0) csq_s[k] = s;
        __syncwarp(0x0003ffffu);
        if (h == 1) csq_s[k] += s;
    }
    __syncthreads();
}

// ---------------------------------------------------------------------------
// Packed pixel-pair dots: 32 LDG.64 + 36 LDS.128 + 288 FFMA2 per thread.
// ---------------------------------------------------------------------------
__device__ __forceinline__ void dot9p2(const float* xp, const u64* centp,
                                       int h, u64 acc2[9])
{
    #pragma unroll
    for (int k = 0; k < 9; k++) acc2[k] = 0ull;

    #pragma unroll
    for (int c8 = 0; c8 < 4; c8++) {
        u64 p2[8];
        #pragma unroll
        for (int i = 0; i < 8; i++)
            p2[i] = *(const u64*)(xp + (size_t)(c8*8 + i)*NPIX);
        #pragma unroll
        for (int k = 0; k < 9; k++) {
            const ulonglong2* cv = (const ulonglong2*)(centp + (k*2 + h)*CP_STR + c8*8);
            #pragma unroll
            for (int i2 = 0; i2 < 4; i2++) {
                ulonglong2 q = cv[i2];
                acc2[k] = fma2(p2[i2*2 + 0], q.x, acc2[k]);
                acc2[k] = fma2(p2[i2*2 + 1], q.y, acc2[k]);
            }
        }
    }
    #pragma unroll
    for (int k = 0; k < 9; k++) {
        u64 o = __shfl_xor_sync(0xffffffffu, acc2[k], 1);
        acc2[k] = add2(acc2[k], o);
    }
}

// ---------------------------------------------------------------------------
// Softmax for this thread's pixel.
// ---------------------------------------------------------------------------
__device__ __forceinline__ void softmax9(const float* dot, const float* csq_s,
                                         int sy, int sx, float* e)
{
    float l[9];
    float m = -1e30f;
    #pragma unroll
    for (int k = 0; k < 9; k++) {
        int cy = sy + (k/3) - 1, cx = sx + (k%3) - 1;
        bool valid = (cy >= 0 && cy < NH && cx >= 0 && cx < NW);
        l[k] = valid ? (2.f*dot[k] - csq_s[k]) : -1e30f;
        m = fmaxf(m, l[k]);
    }
    float ssum = 0.f;
    #pragma unroll
    for (int k = 0; k < 9; k++) {
        e[k] = (l[k] > -1e29f) ? __expf(l[k] - m) : 0.f;
        ssum += e[k];
    }
    float inv = 1.f / ssum;
    #pragma unroll
    for (int k = 0; k < 9; k++) e[k] *= inv;
}

// ---------------------------------------------------------------------------
// K2 (PDL secondary): zero-fill prologue (48 MB, independent of k_means),
// then gridDependencySynchronize, then iteration 0 over FULL blocks.
// 512 CTAs, 256 threads: thread = (pp 0..127, h 0..1); pix == tid.
// ---------------------------------------------------------------------------
__global__ __launch_bounds__(256) void k_iter0(const float* __restrict__ x,
                                               float* __restrict__ out)
{
    __shared__ __align__(16) u64 cent2p[9*2*CP_STR];
    __shared__ float csq_s[9];
    __shared__ u64 Wsh2[256*9];          // packed (w,w)
    __shared__ float dsm[8][9];

    int tid = threadIdx.x;
    int bid = blockIdx.x;

    // independent prologue: streaming zero stores — out4[4194304 .. 7340032)
    {
        float4 z = make_float4(0.f, 0.f, 0.f, 0.f);
        float4* oz = (float4*)out + 4194304 + (size_t)bid*6144;
        #pragma unroll
        for (int j = 0; j < 24; j++) __stcs(&oz[j*256 + tid], z);
    }

    // wait for k_means' g_cent0 to be visible
    cudaGridDependencySynchronize();

    int b   = bid >> 8;
    int blk = bid & 255;
    int sy  = blk >> 4, sx = blk & 15;

    stage_cent2p(g_cent0, cent2p, csq_s, b, sy, sx, tid);

    // phase B
    int pp  = tid >> 1;                 // pixel pair 0..127
    int h   = tid & 1;                  // channel half
    int row = pp >> 3;
    int col2= (pp & 7)*2;
    int n0  = (sy*SS + row)*WW + sx*SS + col2;
    const float* xp = x + (size_t)b*CC*NPIX + (size_t)(h*32)*NPIX + n0;

    u64 acc2[9];
    dot9p2(xp, cent2p, h, acc2);

    float dot[9];
    #pragma unroll
    for (int k = 0; k < 9; k++) {
        float2 d = unpack2(acc2[k]);
        dot[k] = h ? d.y : d.x;
    }

    float e[9];
    softmax9(dot, csq_s, sy, sx, e);

    // pix == tid
    #pragma unroll
    for (int k = 0; k < 9; k++) Wsh2[tid*9 + k] = pack2(e[k], e[k]);

    // den[k] over all 256 pixels
    {
        int wid = tid >> 5, lane = tid & 31;
        #pragma unroll
        for (int k = 0; k < 9; k++) {
            float v = e[k];
            #pragma unroll
            for (int o = 16; o > 0; o >>= 1) v += __shfl_xor_sync(0xffffffffu, v, o);
            if (lane == 0) dsm[wid][k] = v;
        }
        __syncthreads();
        if (tid < 9) {
            float s = 0.f;
            #pragma unroll
            for (int w = 0; w < 8; w++) s += dsm[w][tid];
            g_den0[((size_t)(b*NSP + blk))*9 + tid] = s;
        }
    }

    // phase C (packed): warp wid -> channels [wid*8, wid*8+8).
    int wid = tid >> 5, lane = tid & 31;
    const float* xt = x + (size_t)b*CC*NPIX + (size_t)(sy*SS)*WW + sx*SS;
    float* pdst = g_part + ((size_t)(b*NSP + blk)*9)*64;

    #pragma unroll
    for (int grp = 0; grp < 2; grp++) {
        int cbase = wid*8 + grp*4;
        u64 acc2c[2][9];
        #pragma unroll
        for (int cc = 0; cc < 2; cc++)
            #pragma unroll
            for (int k = 0; k < 9; k++) acc2c[cc][k] = 0ull;

        #pragma unroll
        for (int j = 0; j < 8; j++) {
            int px = j*32 + lane;
            int prow = px >> 4, pcol = px & 15;
            u64 w2[9];
            #pragma unroll
            for (int k = 0; k < 9; k++) w2[k] = Wsh2[px*9 + k];
            #pragma unroll
            for (int cc = 0; cc < 2; cc++) {
                float pv0 = xt[(size_t)(cbase + 2*cc + 0)*NPIX + prow*WW + pcol];
                float pv1 = xt[(size_t)(cbase + 2*cc + 1)*NPIX + prow*WW + pcol];
                u64 pv2 = pack2(pv0, pv1);
                #pragma unroll
                for (int k = 0; k < 9; k++)
                    acc2c[cc][k] = fma2(pv2, w2[k], acc2c[cc][k]);
            }
        }
        float acc[4][9];
        #pragma unroll
        for (int cc = 0; cc < 2; cc++)
            #pragma unroll
            for (int k = 0; k < 9; k++) {
                float2 a = unpack2(acc2c[cc][k]);
                acc[2*cc][k] = a.x; acc[2*cc+1][k] = a.y;
            }
        #pragma unroll
        for (int cc = 0; cc < 4; cc++)
            #pragma unroll
            for (int k = 0; k < 9; k++)
                #pragma unroll
                for (int o = 16; o > 0; o >>= 1)
                    acc[cc][k] += __shfl_xor_sync(0xffffffffu, acc[cc][k], o);
        #pragma unroll
        for (int k = 0; k < 9; k++) {
            if (lane == k) {
                #pragma unroll
                for (int cc = 0; cc < 4; cc++)
                    pdst[(size_t)k*64 + cbase + cc] = acc[cc][k];
            }
        }
    }
}

// ---------------------------------------------------------------------------
// K3 (PDL secondary): zero-fill prologue (16 MB, independent), then sync,
// then gather centroid update. grid = 512 (b,s), block = 256.
// ---------------------------------------------------------------------------
__global__ __launch_bounds__(256) void k_update(float* __restrict__ out)
{
    int tid = threadIdx.x;
    int bid = blockIdx.x;

    // independent prologue: streaming zero stores — out4[7340032 .. 8388608)
    {
        float4 z = make_float4(0.f, 0.f, 0.f, 0.f);
        float4* oz = (float4*)out + 7340032 + (size_t)bid*2048;
        #pragma unroll
        for (int j = 0; j < 8; j++) __stcs(&oz[j*256 + tid], z);
    }

    // wait for k_iter0's g_part/g_den0
    cudaGridDependencySynchronize();

    int b   = bid >> 8;
    int s   = bid & 255;
    int sy  = s >> 4, sx = s & 15;

    __shared__ float dsm[9];
    if (tid < 9) {
        int dy = tid/3 - 1, dx = tid%3 - 1;
        int ny = sy + dy, nx = sx + dx;
        float d = 0.f;
        if (ny >= 0 && ny < NH && nx >= 0 && nx < NW)
            d = g_den0[((size_t)(b*NSP + ny*NW + nx))*9 + (8 - tid)];
        dsm[tid] = d;
    }
    __syncthreads();

    if (tid < 64) {
        int c = tid;
        float den = 0.f;
        #pragma unroll
        for (int j = 0; j < 9; j++) den += dsm[j];

        float num = 0.f;
        #pragma unroll
        for (int j = 0; j < 9; j++) {
            int dy = j/3 - 1, dx = j%3 - 1;
            int ny = sy + dy, nx = sx + dx;
            if (ny >= 0 && ny < NH && nx >= 0 && nx < NW)
                num += g_part[((size_t)((b*NSP + ny*NW + nx)*9 + (8 - j)))*64 + c];
        }
        g_cent1[((size_t)(b*NSP + s))*CC + c] = num / (den + 1e-16f);
    }
}

// ---------------------------------------------------------------------------
// K4 (PDL secondary): sync, then final weights over FULL blocks, scattered
// (evict-first) into the pre-zeroed output. 512 CTAs, 256 threads.
// ---------------------------------------------------------------------------
__global__ __launch_bounds__(256) void k_final(const float* __restrict__ x,
                                               float* __restrict__ out)
{
    __shared__ __align__(16) u64 cent2p[9*2*CP_STR];
    __shared__ float csq_s[9];

    int bid = blockIdx.x;
    int b   = bid >> 8;
    int blk = bid & 255;
    int sy  = blk >> 4, sx = blk & 15;
    int tid = threadIdx.x;

    // wait for k_update's g_cent1 (launch setup overlapped via PDL)
    cudaGridDependencySynchronize();

    stage_cent2p(g_cent1, cent2p, csq_s, b, sy, sx, tid);

    int pp  = tid >> 1;
    int h   = tid & 1;
    int row = pp >> 3;
    int col2= (pp & 7)*2;
    int n0  = (sy*SS + row)*WW + sx*SS + col2;
    const float* xp = x + (size_t)b*CC*NPIX + (size_t)(h*32)*NPIX + n0;

    u64 acc2[9];
    dot9p2(xp, cent2p, h, acc2);

    float dot[9];
    #pragma unroll
    for (int k = 0; k < 9; k++) {
        float2 d = unpack2(acc2[k]);
        dot[k] = h ? d.y : d.x;
    }

    int n = n0 + h;                     // this thread's pixel index
    float e[9];
    softmax9(dot, csq_s, sy, sx, e);

    float* obase = out + ((size_t)b*NSP << 16);
    #pragma unroll
    for (int k = 0; k < 9; k++) {
        int cy = sy + (k/3) - 1, cx = sx + (k%3) - 1;
        if (cy >= 0 && cy < NH && cx >= 0 && cx < NW)
            __stcs(&obase[((size_t)(cy*NW + cx) << 16) + n], e[k]);
    }
}

// ---------------------------------------------------------------------------
extern "C" void kernel_launch(void* const* d_in, const int* in_sizes, int n_in,
                              void* d_out, int out_size)
{
    const float* x = (const float*)d_in[0];
    float* out = (float*)d_out;

    // K1: normal launch
    k_means<<<BB*CC*16, 256>>>(x, out);

    // K2..K4: programmatic dependent launches (prologue overlaps predecessor)
    cudaLaunchAttribute attr[1];
    attr[0].id = cudaLaunchAttributeProgrammaticStreamSerialization;
    attr[0].val.programmaticStreamSerializationAllowed = 1;

    cudaLaunchConfig_t cfg = {};
    cfg.blockDim = dim3(256, 1, 1);
    cfg.attrs = attr;
    cfg.numAttrs = 1;
    cfg.stream = 0;

    cfg.gridDim = dim3(BB*NSP, 1, 1);
    cudaLaunchKernelEx(&cfg, k_iter0, x, out);
    cudaLaunchKernelEx(&cfg, k_update, out);
    cudaLaunchKernelEx(&cfg, k_final, x, out);
}